// round 16
// baseline (speedup 1.0000x reference)
#include <cuda_runtime.h>
#include <cuda_bf16.h>

#define LGT      16
#define NROWS    4096
#define DCOLS    16000              // CLASSNUM * LGT
#define NTHREADS 1024
#define NWORKERS (152 * 2)          // 304 persistent CTAs; 2/SM
#define NCHUNKS  (NROWS * 2)        // half-row work units: 8192
#define VEC_HALF (DCOLS / 4 / 2)    // 2000 float4 per half-row

__device__ float        g_acc = 0.0f;
__device__ unsigned int g_cnt = 0u;

__global__ __launch_bounds__(NTHREADS, 2)
void rvsml_loss_kernel(const float* __restrict__ inputs,
                       const float* __restrict__ labels,
                       float* __restrict__ out) {
    const int tid  = threadIdx.x;
    const int wid  = tid >> 5;
    const int lane = tid & 31;

    float total = 0.0f;   // per-thread running contribution

    // Half-row work units, interleaved: 8192 / 304 = 26.95 per CTA ->
    // 27 vs 26 units = +0.2% imbalance (vs +3.9% at whole-row units).
    // Linearity: each chunk contributes W_row * sq_chunk independently.
    for (int t = blockIdx.x; t < NCHUNKS; t += NWORKERS) {
        const int row  = t >> 1;
        const int half = t & 1;

        // ---- Labels (warp-local broadcast; L1/L2-hot) ----
        const float* lab = labels + row * (LGT + 1);
        float lv = (lane <= LGT) ? __ldg(lab + lane) : 0.0f;
        const int   c = (int)__shfl_sync(0xFFFFFFFFu, lv, LGT);
        const float w = (lane < LGT) ? lv : 0.0f;
        float W = w;
        #pragma unroll
        for (int off = 16; off > 0; off >>= 1)
            W += __shfl_xor_sync(0xFFFFFFFFu, W, off);

        // ---- Stream this half-row: block-thread-strided cached loads ----
        const float4* p =
            reinterpret_cast<const float4*>(inputs + (size_t)row * DCOLS)
            + half * VEC_HALF;
        float sq = 0.0f;
        #pragma unroll 2
        for (int i = tid; i < VEC_HALF; i += NTHREADS) {
            float4 v = p[i];
            sq = fmaf(v.x, v.x, sq);
            sq = fmaf(v.y, v.y, sq);
            sq = fmaf(v.z, v.z, sq);
            sq = fmaf(v.w, v.w, sq);
        }
        total = fmaf(W, sq, total);

        // ---- Gather term, once per row (chunk-half 0, warp 0) ----
        if (half == 0 && wid == 0 && lane < LGT) {
            const float g = __ldg(inputs + (size_t)row * DCOLS + c * LGT + lane);
            total = fmaf(w, 1.0f - 2.0f * g, total);
        }
    }

    // ---- Epilogue: one block reduce + one global atomic per CTA ----
    __shared__ float warp_sums[NTHREADS / 32];
    #pragma unroll
    for (int off = 16; off > 0; off >>= 1)
        total += __shfl_xor_sync(0xFFFFFFFFu, total, off);
    if (lane == 0) warp_sums[wid] = total;
    __syncthreads();

    if (tid < 32) {
        float v = warp_sums[tid];   // NTHREADS/32 == 32 exactly
        #pragma unroll
        for (int off = 16; off > 0; off >>= 1)
            v += __shfl_xor_sync(0xFFFFFFFFu, v, off);

        if (tid == 0) {
            atomicAdd(&g_acc, v);
            __threadfence();
            const unsigned done = atomicAdd(&g_cnt, 1u);
            if (done == NWORKERS - 1) {
                // All contributions visible (each CTA fenced before its
                // counter increment). Read + reset for the next graph replay.
                const float t2 = atomicExch(&g_acc, 0.0f);
                out[0] = t2 * (1.0f / (float)NROWS);
                g_cnt = 0u;
                __threadfence();
            }
        }
    }
}

extern "C" void kernel_launch(void* const* d_in, const int* in_sizes, int n_in,
                              void* d_out, int out_size) {
    const float* inputs = (const float*)d_in[0];
    const float* labels = (const float*)d_in[1];
    float* out = (float*)d_out;

    rvsml_loss_kernel<<<NWORKERS, NTHREADS>>>(inputs, labels, out);
}

// round 17
// speedup vs baseline: 1.0719x; 1.0719x over previous
#include <cuda_runtime.h>
#include <cuda_bf16.h>

#define LGT       16
#define NROWS     4096
#define DCOLS     16000             // CLASSNUM * LGT
#define NTHREADS  1024
#define NWORKERS  (152 * 2)         // 304 persistent CTAs; 2/SM
#define BODY_PER  13                // whole rows per CTA in the body
#define BODY_ROWS (BODY_PER * NWORKERS)   // 3952
#define TAIL_UNITS ((NROWS - BODY_ROWS) * 4)  // 144 rows * 4 quarters = 576
#define VEC_Q     (DCOLS / 4 / 4)   // 1000 float4 per quarter-row

__device__ float        g_acc = 0.0f;
__device__ unsigned int g_cnt = 0u;

__global__ __launch_bounds__(NTHREADS, 2)
void rvsml_loss_kernel(const float* __restrict__ inputs,
                       const float* __restrict__ labels,
                       float* __restrict__ out) {
    const int tid  = threadIdx.x;
    const int wid  = tid >> 5;
    const int lane = tid & 31;
    const int bid  = blockIdx.x;

    float total = 0.0f;   // per-thread running contribution

    // ===== Body: exactly 13 whole rows per CTA (rows 0..3951), =====
    // ===== interleaved — identical inner loop to the best (R14) config =====
    #pragma unroll 1
    for (int k = 0; k < BODY_PER; k++) {
        const int row = bid + k * NWORKERS;

        // ---- Labels (warp-local broadcast; L1-hot) ----
        const float* lab = labels + row * (LGT + 1);
        float lv = (lane <= LGT) ? __ldg(lab + lane) : 0.0f;
        const int   c = (int)__shfl_sync(0xFFFFFFFFu, lv, LGT);
        const float w = (lane < LGT) ? lv : 0.0f;
        float W = w;
        #pragma unroll
        for (int off = 16; off > 0; off >>= 1)
            W += __shfl_xor_sync(0xFFFFFFFFu, W, off);

        // ---- Stream the row ----
        const float4* rowp =
            reinterpret_cast<const float4*>(inputs + (size_t)row * DCOLS);
        float sq = 0.0f;
        #pragma unroll 4
        for (int i = tid; i < DCOLS / 4; i += NTHREADS) {
            float4 v = rowp[i];
            sq = fmaf(v.x, v.x, sq);
            sq = fmaf(v.y, v.y, sq);
            sq = fmaf(v.z, v.z, sq);
            sq = fmaf(v.w, v.w, sq);
        }
        total = fmaf(W, sq, total);

        // ---- Gather term, once per row (warp 0 lanes 0..15; L2-hot) ----
        if (wid == 0 && lane < LGT) {
            const float g = __ldg(inputs + (size_t)row * DCOLS + c * LGT + lane);
            total = fmaf(w, 1.0f - 2.0f * g, total);
        }
    }

    // ===== Tail: rows 3952..4095 as quarter-row units (576 units) =====
    // Max 2 units/CTA -> +0.2% critical-path imbalance vs +3.9% whole-row.
    for (int u = bid; u < TAIL_UNITS; u += NWORKERS) {
        const int row = BODY_ROWS + (u >> 2);
        const int q   = u & 3;

        const float* lab = labels + row * (LGT + 1);
        float lv = (lane <= LGT) ? __ldg(lab + lane) : 0.0f;
        const int   c = (int)__shfl_sync(0xFFFFFFFFu, lv, LGT);
        const float w = (lane < LGT) ? lv : 0.0f;
        float W = w;
        #pragma unroll
        for (int off = 16; off > 0; off >>= 1)
            W += __shfl_xor_sync(0xFFFFFFFFu, W, off);

        const float4* p =
            reinterpret_cast<const float4*>(inputs + (size_t)row * DCOLS)
            + q * VEC_Q;
        float sq = 0.0f;
        if (tid < VEC_Q) {          // 1000 of 1024 threads, one load each
            float4 v = p[tid];
            sq = fmaf(v.x, v.x, sq);
            sq = fmaf(v.y, v.y, sq);
            sq = fmaf(v.z, v.z, sq);
            sq = fmaf(v.w, v.w, sq);
        }
        total = fmaf(W, sq, total);

        if (q == 0 && wid == 0 && lane < LGT) {
            const float g = __ldg(inputs + (size_t)row * DCOLS + c * LGT + lane);
            total = fmaf(w, 1.0f - 2.0f * g, total);
        }
    }

    // ===== Epilogue: one block reduce + one global atomic per CTA =====
    __shared__ float warp_sums[NTHREADS / 32];
    #pragma unroll
    for (int off = 16; off > 0; off >>= 1)
        total += __shfl_xor_sync(0xFFFFFFFFu, total, off);
    if (lane == 0) warp_sums[wid] = total;
    __syncthreads();

    if (tid < 32) {
        float v = warp_sums[tid];   // NTHREADS/32 == 32 exactly
        #pragma unroll
        for (int off = 16; off > 0; off >>= 1)
            v += __shfl_xor_sync(0xFFFFFFFFu, v, off);

        if (tid == 0) {
            atomicAdd(&g_acc, v);
            __threadfence();
            const unsigned done = atomicAdd(&g_cnt, 1u);
            if (done == NWORKERS - 1) {
                // All contributions visible (each CTA fenced before its
                // counter increment). Read + reset for the next graph replay.
                const float t = atomicExch(&g_acc, 0.0f);
                out[0] = t * (1.0f / (float)NROWS);
                g_cnt = 0u;
                __threadfence();
            }
        }
    }
}

extern "C" void kernel_launch(void* const* d_in, const int* in_sizes, int n_in,
                              void* d_out, int out_size) {
    const float* inputs = (const float*)d_in[0];
    const float* labels = (const float*)d_in[1];
    float* out = (float*)d_out;

    rvsml_loss_kernel<<<NWORKERS, NTHREADS>>>(inputs, labels, out);
}